// round 5
// baseline (speedup 1.0000x reference)
#include <cuda_runtime.h>

// B=8, N=1024, D=256, H=512, M=256, O=256, 4H=2048

__device__ float g_xproj[8 * 1024 * 2048];
__device__ float g_h    [8 * 1024 * 512];
__device__ float g_t1   [8 * 1024 * 256];
__device__ float g_t2   [8 * 1024 * 256];
__device__ float g_ax   [8 * 1024 * 256];
__device__ float g_av   [8 * 1024 * 256];
__device__ float g_scores[8 * 1024 * 1024];
__device__ float g_sagg [8 * 1024 * 512];
__device__ float g_agg  [8 * 1024 * 256];
__device__ int   g_hasnb[8 * 1024];
__device__ unsigned g_flags[128];

__device__ __forceinline__ unsigned ld_acq(const unsigned* p) {
    unsigned v;
    asm volatile("ld.acquire.gpu.global.u32 %0, [%1];" : "=r"(v) : "l"(p) : "memory");
    return v;
}
__device__ __forceinline__ void st_rel(unsigned* p, unsigned v) {
    asm volatile("st.release.gpu.global.u32 [%0], %1;" :: "l"(p), "r"(v) : "memory");
}

__global__ void reset_kernel() {
    if (threadIdx.x < 128) g_flags[threadIdx.x] = 0u;
}

// ---------- persistent LSTM: 128 CTAs x 256 thr; CTA owns 4 j-cols (16 gate rows) ----------
__global__ __launch_bounds__(256, 1) void lstm_kernel(const float* __restrict__ Whh)
{
    __shared__ __align__(16) float hs[8 * 512];
    __shared__ float gsum[16][8];

    const int tid  = threadIdx.x;
    const int w    = tid >> 5;
    const int lane = tid & 31;
    const int j0   = blockIdx.x * 4;

    float wreg0[16], wreg1[16];
    {
        int lr0 = 2 * w, lr1 = 2 * w + 1;
        int grow0 = (lr0 >> 2) * 512 + j0 + (lr0 & 3);
        int grow1 = (lr1 >> 2) * 512 + j0 + (lr1 & 3);
        #pragma unroll
        for (int i = 0; i < 16; i++) {
            wreg0[i] = Whh[(size_t)grow0 * 512 + lane + (i << 5)];
            wreg1[i] = Whh[(size_t)grow1 * 512 + lane + (i << 5)];
        }
    }

    float c_st = 0.f;
    const int ub  = lane >> 2;
    const int ujl = lane & 3;

    for (int t = 0; t < 1024; ++t) {
        if (tid < 128) {
            while (ld_acq(&g_flags[tid]) < (unsigned)t) {
                __nanosleep(64);
            }
        }
        __syncthreads();

        if (t == 0) {
            #pragma unroll
            for (int q = 0; q < 4; q++)
                *(float4*)&hs[(tid + 256 * q) * 4] = make_float4(0.f, 0.f, 0.f, 0.f);
        } else {
            #pragma unroll
            for (int q = 0; q < 4; q++) {
                int flat = (tid + 256 * q) * 4;
                int b = flat >> 9, k = flat & 511;
                *(float4*)&hs[flat] =
                    *(const float4*)&g_h[((size_t)(b << 10) + (t - 1)) * 512 + k];
            }
        }

        float xq0 = 0.f, xq1 = 0.f, xq2 = 0.f, xq3 = 0.f;
        if (tid < 32) {
            size_t base = ((size_t)(ub << 10) + t) * 2048 + j0 + ujl;
            xq0 = g_xproj[base];
            xq1 = g_xproj[base + 512];
            xq2 = g_xproj[base + 1024];
            xq3 = g_xproj[base + 1536];
        }
        __syncthreads();

        float acc0[8], acc1[8];
        #pragma unroll
        for (int b = 0; b < 8; b++) { acc0[b] = 0.f; acc1[b] = 0.f; }
        #pragma unroll
        for (int i = 0; i < 16; i++) {
            const float w0 = wreg0[i], w1 = wreg1[i];
            const int k = lane + (i << 5);
            #pragma unroll
            for (int b = 0; b < 8; b++) {
                float hv = hs[b * 512 + k];
                acc0[b] = fmaf(w0, hv, acc0[b]);
                acc1[b] = fmaf(w1, hv, acc1[b]);
            }
        }
        #pragma unroll
        for (int off = 16; off > 0; off >>= 1) {
            #pragma unroll
            for (int b = 0; b < 8; b++) {
                acc0[b] += __shfl_xor_sync(0xffffffffu, acc0[b], off);
                acc1[b] += __shfl_xor_sync(0xffffffffu, acc1[b], off);
            }
        }
        if (lane < 16) {
            int rsel = lane >> 3;
            int b = lane & 7;
            gsum[2 * w + rsel][b] = rsel ? acc1[b] : acc0[b];
        }
        __syncthreads();

        if (tid < 32) {
            float gi = gsum[0  + ujl][ub] + xq0;
            float gf = gsum[4  + ujl][ub] + xq1;
            float gg = gsum[8  + ujl][ub] + xq2;
            float go = gsum[12 + ujl][ub] + xq3;
            float si = 1.f / (1.f + expf(-gi));
            float sf = 1.f / (1.f + expf(-gf));
            float so = 1.f / (1.f + expf(-go));
            float tg = tanhf(gg);
            c_st = sf * c_st + si * tg;
            float hN = so * tanhf(c_st);
            g_h[((size_t)(ub << 10) + t) * 512 + j0 + ujl] = hN;
            __threadfence();
            __syncwarp();
            if (lane == 0) st_rel(&g_flags[blockIdx.x], (unsigned)(t + 1));
        }
    }
}

// ---------- generic tiled fp32 GEMM: C = A @ op(B) (+bias[+bias2]) [ReLU] [ACC] [rowmask] ----------
// TB==0: B is [N,K] row-major (NT). TB==1: B is [K,N] (NN). M,N %128==0, K%8==0.
template<int TB, bool RELU, bool ACC>
__global__ __launch_bounds__(256) void gemm_kernel(
    const float* __restrict__ A, int lda, long long strideA,
    const float* __restrict__ B, int ldb, long long strideB,
    float* __restrict__ C, int ldc, long long strideC,
    int M, int N, int K,
    const float* __restrict__ bias, const float* __restrict__ bias2,
    const int* __restrict__ rowmask)
{
    __shared__ __align__(16) float As[2][8][128];
    __shared__ __align__(16) float Bs[2][8][128];

    const int tid = threadIdx.x;
    const int m0 = blockIdx.y * 128;
    const int n0 = blockIdx.x * 128;
    A += (long long)blockIdx.z * strideA;
    B += (long long)blockIdx.z * strideB;
    C += (long long)blockIdx.z * strideC;

    const int ar   = tid >> 1;
    const int aseg = (tid & 1) * 4;
    const int bk   = tid >> 5;
    const int bn   = (tid & 31) * 4;
    const int nk   = K >> 3;

    {
        float4 a4 = *(const float4*)(A + (size_t)(m0 + ar) * lda + aseg);
        As[0][aseg + 0][ar] = a4.x; As[0][aseg + 1][ar] = a4.y;
        As[0][aseg + 2][ar] = a4.z; As[0][aseg + 3][ar] = a4.w;
        if (TB == 0) {
            float4 b4 = *(const float4*)(B + (size_t)(n0 + ar) * ldb + aseg);
            Bs[0][aseg + 0][ar] = b4.x; Bs[0][aseg + 1][ar] = b4.y;
            Bs[0][aseg + 2][ar] = b4.z; Bs[0][aseg + 3][ar] = b4.w;
        } else {
            *(float4*)&Bs[0][bk][bn] = *(const float4*)(B + (size_t)bk * ldb + n0 + bn);
        }
    }
    __syncthreads();

    float acc[8][8];
    #pragma unroll
    for (int i = 0; i < 8; i++)
        #pragma unroll
        for (int j = 0; j < 8; j++) acc[i][j] = 0.f;

    const int tm = (tid >> 4) << 3;
    const int tn = (tid & 15) << 3;

    for (int kt = 0; kt < nk; ++kt) {
        const int cur = kt & 1, nxt = cur ^ 1;
        float4 na, nb;
        if (kt + 1 < nk) {
            const int k0 = (kt + 1) << 3;
            na = *(const float4*)(A + (size_t)(m0 + ar) * lda + k0 + aseg);
            if (TB == 0)
                nb = *(const float4*)(B + (size_t)(n0 + ar) * ldb + k0 + aseg);
            else
                nb = *(const float4*)(B + (size_t)(k0 + bk) * ldb + n0 + bn);
        }
        #pragma unroll
        for (int kk = 0; kk < 8; ++kk) {
            float4 aa0 = *(const float4*)&As[cur][kk][tm];
            float4 aa1 = *(const float4*)&As[cur][kk][tm + 4];
            float4 bb0 = *(const float4*)&Bs[cur][kk][tn];
            float4 bb1 = *(const float4*)&Bs[cur][kk][tn + 4];
            float av_[8] = {aa0.x, aa0.y, aa0.z, aa0.w, aa1.x, aa1.y, aa1.z, aa1.w};
            float bv_[8] = {bb0.x, bb0.y, bb0.z, bb0.w, bb1.x, bb1.y, bb1.z, bb1.w};
            #pragma unroll
            for (int i = 0; i < 8; i++)
                #pragma unroll
                for (int j = 0; j < 8; j++)
                    acc[i][j] = fmaf(av_[i], bv_[j], acc[i][j]);
        }
        if (kt + 1 < nk) {
            As[nxt][aseg + 0][ar] = na.x; As[nxt][aseg + 1][ar] = na.y;
            As[nxt][aseg + 2][ar] = na.z; As[nxt][aseg + 3][ar] = na.w;
            if (TB == 0) {
                Bs[nxt][aseg + 0][ar] = nb.x; Bs[nxt][aseg + 1][ar] = nb.y;
                Bs[nxt][aseg + 2][ar] = nb.z; Bs[nxt][aseg + 3][ar] = nb.w;
            } else {
                *(float4*)&Bs[nxt][bk][bn] = nb;
            }
        }
        __syncthreads();
    }

    float bvv[8];
    #pragma unroll
    for (int j = 0; j < 8; j++) {
        float b = bias ? bias[n0 + tn + j] : 0.f;
        if (bias2) b += bias2[n0 + tn + j];
        bvv[j] = b;
    }
    #pragma unroll
    for (int i = 0; i < 8; i++) {
        const int row = m0 + tm + i;
        float keep = 1.f;
        if (rowmask) keep = rowmask[row] ? 1.f : 0.f;
        float out[8];
        #pragma unroll
        for (int j = 0; j < 8; j++) {
            float v = acc[i][j] + bvv[j];
            if (RELU) v = fmaxf(v, 0.f);
            out[j] = v * keep;
        }
        float* Cp = C + (size_t)row * ldc + n0 + tn;
        if (ACC) {
            float4 o0 = *(const float4*)Cp;
            float4 o1 = *(const float4*)(Cp + 4);
            out[0] += o0.x; out[1] += o0.y; out[2] += o0.z; out[3] += o0.w;
            out[4] += o1.x; out[5] += o1.y; out[6] += o1.z; out[7] += o1.w;
        }
        *(float4*)Cp       = make_float4(out[0], out[1], out[2], out[3]);
        *(float4*)(Cp + 4) = make_float4(out[4], out[5], out[6], out[7]);
    }
}

// ---------- masked softmax per row (in place) + has-neighbor flag ----------
__global__ __launch_bounds__(256) void softmax_kernel(
    float* __restrict__ S, const int* __restrict__ adj, int* __restrict__ hasnb)
{
    __shared__ float sred[32];
    const int r = blockIdx.x;
    const int i = r & 1023;
    const int tid = threadIdx.x;
    float* Sr = S + (size_t)r * 1024;
    const int* Ar = adj + (size_t)r * 1024;

    float v[4]; int ok[4];
    float mx = -3.0e38f;
    #pragma unroll
    for (int q = 0; q < 4; q++) {
        int j = tid + 256 * q;
        ok[q] = (Ar[j] > 0) && (j != i);
        v[q] = Sr[j];
        if (ok[q]) mx = fmaxf(mx, v[q]);
    }
    #pragma unroll
    for (int off = 16; off > 0; off >>= 1)
        mx = fmaxf(mx, __shfl_xor_sync(0xffffffffu, mx, off));
    if ((tid & 31) == 0) sred[tid >> 5] = mx;
    __syncthreads();
    if (tid < 32) {
        float m2 = (tid < 8) ? sred[tid] : -3.0e38f;
        #pragma unroll
        for (int off = 4; off > 0; off >>= 1)
            m2 = fmaxf(m2, __shfl_xor_sync(0xffffffffu, m2, off));
        if (tid == 0) sred[0] = m2;
    }
    __syncthreads();
    const float rowmax = sred[0];
    const bool any = rowmax > -1.0e37f;

    float e[4];
    float s = 0.f;
    #pragma unroll
    for (int q = 0; q < 4; q++) {
        e[q] = ok[q] ? expf(v[q] - rowmax) : 0.f;
        s += e[q];
    }
    #pragma unroll
    for (int off = 16; off > 0; off >>= 1)
        s += __shfl_xor_sync(0xffffffffu, s, off);
    __syncthreads();
    if ((tid & 31) == 0) sred[tid >> 5] = s;
    __syncthreads();
    if (tid < 32) {
        float s2 = (tid < 8) ? sred[tid] : 0.f;
        #pragma unroll
        for (int off = 4; off > 0; off >>= 1)
            s2 += __shfl_xor_sync(0xffffffffu, s2, off);
        if (tid == 0) sred[0] = s2;
    }
    __syncthreads();
    const float inv = any ? (1.f / sred[0]) : 0.f;
    #pragma unroll
    for (int q = 0; q < 4; q++)
        Sr[tid + 256 * q] = e[q] * inv;
    if (tid == 0) hasnb[r] = any ? 1 : 0;
}

extern "C" void kernel_launch(void* const* d_in, const int* in_sizes, int n_in,
                              void* d_out, int out_size)
{
    const float* feats  = (const float*)d_in[0];
    const int*   adj    = (const int*)  d_in[1];
    const float* W_ih   = (const float*)d_in[2];
    const float* W_hh   = (const float*)d_in[3];
    const float* b_ih   = (const float*)d_in[4];
    const float* b_hh   = (const float*)d_in[5];
    const float* gx_W1  = (const float*)d_in[6];
    const float* gx_b1  = (const float*)d_in[7];
    const float* gx_W2  = (const float*)d_in[8];
    const float* gx_b2  = (const float*)d_in[9];
    const float* gz_W1  = (const float*)d_in[10];
    const float* gz_b1  = (const float*)d_in[11];
    const float* gz_W2  = (const float*)d_in[12];
    const float* gz_b2  = (const float*)d_in[13];
    const float* gv_W1  = (const float*)d_in[14];
    const float* gv_b1  = (const float*)d_in[15];
    const float* gv_W2  = (const float*)d_in[16];
    const float* gv_b2  = (const float*)d_in[17];
    const float* gn_W1  = (const float*)d_in[18];
    const float* gn_b1  = (const float*)d_in[19];
    const float* gn_W2  = (const float*)d_in[20];
    const float* gn_b2  = (const float*)d_in[21];
    const float* out_W  = (const float*)d_in[22];
    const float* out_b  = (const float*)d_in[23];
    float* out = (float*)d_out;

    float *xproj, *h, *t1, *t2, *ax, *av, *scores, *sagg, *agg;
    int* hasnb;
    cudaGetSymbolAddress((void**)&xproj,  g_xproj);
    cudaGetSymbolAddress((void**)&h,      g_h);
    cudaGetSymbolAddress((void**)&t1,     g_t1);
    cudaGetSymbolAddress((void**)&t2,     g_t2);
    cudaGetSymbolAddress((void**)&ax,     g_ax);
    cudaGetSymbolAddress((void**)&av,     g_av);
    cudaGetSymbolAddress((void**)&scores, g_scores);
    cudaGetSymbolAddress((void**)&sagg,   g_sagg);
    cudaGetSymbolAddress((void**)&agg,    g_agg);
    cudaGetSymbolAddress((void**)&hasnb,  g_hasnb);

    reset_kernel<<<1, 128>>>();

    // x_proj = feats @ W_ih^T + (b_ih + b_hh) : [8192,2048], K=256
    gemm_kernel<0, false, false><<<dim3(16, 64, 1), 256>>>(
        feats, 256, 0, W_ih, 256, 0, xproj, 2048, 0,
        8192, 2048, 256, b_ih, b_hh, nullptr);

    lstm_kernel<<<128, 256>>>(W_hh);

    // ax = MLP_gx(h)
    gemm_kernel<0, true , false><<<dim3(2, 64, 1), 256>>>(
        h, 512, 0, gx_W1, 512, 0, t1, 256, 0, 8192, 256, 512, gx_b1, nullptr, nullptr);
    gemm_kernel<0, false, false><<<dim3(2, 64, 1), 256>>>(
        t1, 256, 0, gx_W2, 256, 0, ax, 256, 0, 8192, 256, 256, gx_b2, nullptr, nullptr);

    // av = MLP_gv(h)
    gemm_kernel<0, true , false><<<dim3(2, 64, 1), 256>>>(
        h, 512, 0, gv_W1, 512, 0, t1, 256, 0, 8192, 256, 512, gv_b1, nullptr, nullptr);
    gemm_kernel<0, false, false><<<dim3(2, 64, 1), 256>>>(
        t1, 256, 0, gv_W2, 256, 0, av, 256, 0, 8192, 256, 256, gv_b2, nullptr, nullptr);

    // scores[b] = ax[b] @ av[b]^T
    gemm_kernel<0, false, false><<<dim3(8, 8, 8), 256>>>(
        ax, 256, 1024LL * 256, av, 256, 1024LL * 256,
        scores, 1024, 1024LL * 1024, 1024, 1024, 256, nullptr, nullptr, nullptr);

    softmax_kernel<<<8192, 256>>>(scores, adj, hasnb);

    // sagg[b] = w[b] @ h[b]
    gemm_kernel<1, false, false><<<dim3(4, 8, 8), 256>>>(
        scores, 1024, 1024LL * 1024, h, 512, 1024LL * 512,
        sagg, 512, 1024LL * 512, 1024, 512, 1024, nullptr, nullptr, nullptr);

    // agg = MLP_gn(MLP_gz(sagg)) with isolated-node zeroing
    gemm_kernel<0, true , false><<<dim3(2, 64, 1), 256>>>(
        sagg, 512, 0, gz_W1, 512, 0, t1, 256, 0, 8192, 256, 512, gz_b1, nullptr, nullptr);
    gemm_kernel<0, false, false><<<dim3(2, 64, 1), 256>>>(
        t1, 256, 0, gz_W2, 256, 0, t2, 256, 0, 8192, 256, 256, gz_b2, nullptr, nullptr);
    gemm_kernel<0, true , false><<<dim3(2, 64, 1), 256>>>(
        t2, 256, 0, gn_W1, 256, 0, t1, 256, 0, 8192, 256, 256, gn_b1, nullptr, nullptr);
    gemm_kernel<0, false, false><<<dim3(2, 64, 1), 256>>>(
        t1, 256, 0, gn_W2, 256, 0, agg, 256, 0, 8192, 256, 256, gn_b2, nullptr, hasnb);

    // out = h @ out_W[:, :512]^T + out_b ; out += agg @ out_W[:, 512:]^T
    gemm_kernel<0, false, false><<<dim3(2, 64, 1), 256>>>(
        h, 512, 0, out_W, 768, 0, out, 256, 0, 8192, 256, 512, out_b, nullptr, nullptr);
    gemm_kernel<0, false, true ><<<dim3(2, 64, 1), 256>>>(
        agg, 256, 0, out_W + 512, 768, 0, out, 256, 0, 8192, 256, 256, nullptr, nullptr, nullptr);
}